// round 13
// baseline (speedup 1.0000x reference)
#include <cuda_runtime.h>
#include <cuda_bf16.h>
#include <cstdint>
#include <cmath>

#define T_LEN 1024
#define NH    512
#define NI    128
#define BSZ   64
#define DT_C  0.1f

// Hoisted input projection scratch: tanh(x @ x2h), [B, T, H] fp32 (134 MB).
__device__ float g_tanhI[(size_t)BSZ * T_LEN * NH];

typedef unsigned long long ull;

// ---------------------------------------------------------------------------
// helpers
// ---------------------------------------------------------------------------
__device__ __forceinline__ uint32_t smem_u32(const void* p) {
    uint32_t a;
    asm("{ .reg .u64 t; cvta.to.shared.u64 t, %1; cvt.u32.u64 %0, t; }" : "=r"(a) : "l"(p));
    return a;
}
__device__ __forceinline__ uint32_t mapa_sc(uint32_t addr, uint32_t rank) {
    uint32_t r;
    asm("mapa.shared::cluster.u32 %0, %1, %2;" : "=r"(r) : "r"(addr), "r"(rank));
    return r;
}
__device__ __forceinline__ void cluster_sync_() {
    asm volatile("barrier.cluster.arrive.aligned;" ::: "memory");
    asm volatile("barrier.cluster.wait.aligned;" ::: "memory");
}
__device__ __forceinline__ ull pack2(float w) {
    ull r;
    asm("mov.b64 %0, {%1, %1};" : "=l"(r) : "f"(w));
    return r;
}
__device__ __forceinline__ void ffma2(ull& d, ull a, ull b) {
    asm("fma.rn.f32x2 %0, %1, %2, %0;" : "+l"(d) : "l"(a), "l"(b));
}
__device__ __forceinline__ void mbar_init(uint32_t addr, uint32_t count) {
    asm volatile("mbarrier.init.shared.b64 [%0], %1;" :: "r"(addr), "r"(count) : "memory");
}
__device__ __forceinline__ void mbar_expect(uint32_t addr, uint32_t bytes) {
    asm volatile("mbarrier.arrive.expect_tx.shared.b64 _, [%0], %1;"
                 :: "r"(addr), "r"(bytes) : "memory");
}
__device__ __forceinline__ void mbar_wait(uint32_t mbar, uint32_t parity) {
    uint32_t done;
    asm volatile(
        "{\n\t.reg .pred p;\n\t"
        "mbarrier.try_wait.parity.acquire.cluster.shared::cta.b64 p, [%1], %2;\n\t"
        "selp.b32 %0, 1, 0, p;\n\t}"
        : "=r"(done) : "r"(mbar), "r"(parity) : "memory");
    if (!done) {
        asm volatile(
            "{\n\t.reg .pred P1;\n\t"
            "W_%=:\n\t"
            "mbarrier.try_wait.parity.acquire.cluster.shared::cta.b64 P1, [%0], %1, 0x989680;\n\t"
            "@P1 bra.uni D_%=;\n\t"
            "bra.uni W_%=;\n\t"
            "D_%=:\n\t}"
            :: "r"(mbar), "r"(parity) : "memory");
    }
}
__device__ __forceinline__ void fence_async_() {
    asm volatile("fence.proxy.async.shared::cta;" ::: "memory");
}
__device__ __forceinline__ void bulk_dsm(uint32_t dst_cluster, uint32_t src_cta,
                                         uint32_t bytes, uint32_t mbar_cluster) {
    asm volatile(
        "cp.async.bulk.shared::cluster.shared::cta.mbarrier::complete_tx::bytes "
        "[%0], [%1], %2, [%3];"
        :: "r"(dst_cluster), "r"(src_cta), "r"(bytes), "r"(mbar_cluster) : "memory");
}

// ---------------------------------------------------------------------------
// Phase 1: g_tanhI[bt, h] = tanh( x[bt, :] @ x2h[:, h] )
// ---------------------------------------------------------------------------
__global__ void __launch_bounds__(256) phase1_kernel(const float* __restrict__ x,
                                                     const float* __restrict__ x2h) {
    __shared__ float  x_s[16 * 132];
    __shared__ float4 w4_s[128 * 16];
    const int tid = threadIdx.x;
    const int bt0 = blockIdx.x * 16;

    for (int i = tid; i < 512; i += 256) {
        int r = i >> 5, c = i & 31;
        float4 v = *reinterpret_cast<const float4*>(x + (size_t)(bt0 + r) * NI + c * 4);
        *reinterpret_cast<float4*>(x_s + r * 132 + c * 4) = v;
    }

    const int tt = tid & 15;
    const int jc = tid >> 4;
    for (int chunk = 0; chunk < 8; ++chunk) {
        __syncthreads();
        const int jbase = chunk * 64;
        for (int i = tid; i < 2048; i += 256) {
            int k = i >> 4, jq = i & 15;
            w4_s[k * 16 + jq] =
                *reinterpret_cast<const float4*>(x2h + (size_t)k * NH + jbase + jq * 4);
        }
        __syncthreads();
        float a0 = 0.f, a1 = 0.f, a2 = 0.f, a3 = 0.f;
        #pragma unroll 8
        for (int k = 0; k < 128; ++k) {
            float  xv = x_s[tt * 132 + k];
            float4 w  = w4_s[k * 16 + jc];
            a0 = fmaf(xv, w.x, a0); a1 = fmaf(xv, w.y, a1);
            a2 = fmaf(xv, w.z, a2); a3 = fmaf(xv, w.w, a3);
        }
        float4 o = make_float4(tanhf(a0), tanhf(a1), tanhf(a2), tanhf(a3));
        *reinterpret_cast<float4*>(g_tanhI + (size_t)(bt0 + tt) * NH + jbase + jc * 4) = o;
    }
}

// ---------------------------------------------------------------------------
// Phase 2: recurrence. 16 clusters x 8 CTAs x 512 threads (R11 machinery).
// This round: GEMM1 weight column (time-invariant, 64 floats/thread) lives in
// REGISTERS -> removes 64 non-broadcast LDS.32 per thread per step.
//
// SMEM float layout (R11):
//   [0)      wT      64*513 = 32832
//   [32832)  hy4     512*4    (hy[k][m])
//   [34880)  pre     64*4
//   [35136)  stage   8*64*4
//   [37184)  red     8*64*4   ([src][kl][m]; 1KB blocks)
//   [39232)  redout  8*64*4   (local staging [tgt][kl][m])
//   [41280)  hyst    64*4     ([kl][m])
//   [41536)  bias    64
//   [41600)  mbars   red_mbar(8B) + hy_mbar(8B) = 4 floats
//   total 41604 floats = 166416 B
// ---------------------------------------------------------------------------
#define WS        513
#define W_OFF     0
#define HY_OFF    32832
#define PRE_OFF   34880
#define STG_OFF   35136
#define RED_OFF   37184
#define RDO_OFF   39232
#define HYST_OFF  41280
#define BIAS_OFF  41536
#define MBAR_OFF  41600
#define SMEM_FLOATS 41604
#define SMEM_BYTES  (SMEM_FLOATS * 4)

__global__ void __launch_bounds__(512)
rnn_kernel(const float* __restrict__ h2h, const float* __restrict__ bias,
           const float* __restrict__ gamma_v, const float* __restrict__ eps_v,
           float* __restrict__ out_states, float* __restrict__ out_hy) {
    extern __shared__ float sm[];
    float* bias_s = sm + BIAS_OFF;
    ulonglong2* stg2 = reinterpret_cast<ulonglong2*>(sm + STG_OFF);

    const int tid = threadIdx.x;
    uint32_t rank;
    asm("mov.u32 %0, %%cluster_ctarank;" : "=r"(rank));
    const int m_base = (blockIdx.x >> 3) * 4;
    const int J0 = (int)rank * 64;
    const uint32_t smb = smem_u32(sm);
    const uint32_t red_mbar = smb + MBAR_OFF * 4;
    const uint32_t hy_mbar  = smb + MBAR_OFF * 4 + 8;

    // --- init: weights, bias, zero hy4, mbars + phase-0 arms ---
    for (int idx = tid; idx < 64 * 512; idx += 512) {
        int k = idx >> 6, jl = idx & 63;
        sm[W_OFF + jl * WS + k] = h2h[(size_t)k * NH + J0 + jl];
    }
    if (tid < 64) bias_s[tid] = bias[J0 + tid];
    for (int i = tid; i < 2048; i += 512) sm[HY_OFF + i] = 0.f;
    if (tid == 0) {
        mbar_init(red_mbar, 1);
        mbar_init(hy_mbar, 1);
        mbar_expect(red_mbar, 7168);   // 7 peers x 1KB, phase 0
        mbar_expect(hy_mbar, 7168);
    }

    // --- fixed thread mappings (R11) ---
    const int ks = tid >> 6;          // GEMM1 k-split 0..7 (64 k each)
    const int jg = tid & 63;          // GEMM1 local j
    const int k2 = tid;               // GEMM2 k (0..511)
    const int kl_u = tid >> 2;        // update (tid<256): [kl][m]
    const int m_u  = tid & 3;
    const int k_own = J0 + kl_u;

    // bulk issuers: threads 256..262, peer p = (rank + 1 + (tid-256)) & 7
    const bool issuer = (tid >= 256 && tid < 263);
    uint32_t red_dst = 0, red_src = 0, red_mb = 0;
    uint32_t hy_dst = 0, hy_src = 0, hy_mb = 0;
    if (issuer) {
        const uint32_t p = (rank + 1u + (uint32_t)(tid - 256)) & 7u;
        red_dst = mapa_sc(smb + RED_OFF * 4, p) + rank * 1024;
        red_src = smb + RDO_OFF * 4 + p * 1024;
        red_mb  = mapa_sc(red_mbar, p);
        hy_dst  = mapa_sc(smb + HY_OFF * 4, p) + rank * 1024;
        hy_src  = smb + HYST_OFF * 4;
        hy_mb   = mapa_sc(hy_mbar, p);
    }

    float hy_r = 0.f, hz_r = 0.f, g_r = 0.f, e_r = 0.f, tI = 0.f;
    size_t row_base = 0;
    if (tid < 256) {
        g_r = gamma_v[k_own];
        e_r = eps_v[k_own];
        row_base = (size_t)(m_base + m_u) * T_LEN * NH + k_own;
        tI = g_tanhI[row_base];
    }

    __syncthreads();

    // --- GEMM1 weights -> registers (time-invariant per thread) ---
    float wreg[64];
    {
        const float* wcol = sm + W_OFF + jg * WS + ks * 64;
        #pragma unroll
        for (int k = 0; k < 64; ++k) wreg[k] = wcol[k];
    }

    cluster_sync_();   // weights / zeroed hy / armed mbars visible cluster-wide

    const ulonglong2* hyk  = reinterpret_cast<const ulonglong2*>(sm + HY_OFF) + ks * 64;
    const ulonglong2* pre2 = reinterpret_cast<const ulonglong2*>(sm + PRE_OFF);

    for (int t = 0; t < T_LEN; ++t) {
        // ---- wait hy delivery (phase t-1), re-arm next hy phase ----
        if (t) {
            mbar_wait(hy_mbar, (uint32_t)((t + 1) & 1));
            if (tid == 0 && t <= T_LEN - 2) mbar_expect(hy_mbar, 7168);
        }

        // ---- GEMM1 k-split partial: register weights, broadcast hy loads ----
        {
            ull a01 = 0ull, a23 = 0ull;
            #pragma unroll 16
            for (int k = 0; k < 64; ++k) {
                ull w2 = pack2(wreg[k]);
                ulonglong2 h = hyk[k];
                ffma2(a01, w2, h.x);
                ffma2(a23, w2, h.y);
            }
            stg2[ks * 64 + jg] = make_ulonglong2(a01, a23);
        }
        __syncthreads();
        if (tid < 256) {                 // sum 8 partials + bias + tanh
            float s = bias_s[tid >> 2];
            #pragma unroll
            for (int q = 0; q < 8; ++q) s += sm[STG_OFF + q * 256 + tid];
            sm[PRE_OFF + tid] = tanhf(s);
        }
        __syncthreads();

        // ---- GEMM2 partial: 1 k/thread over my 64-j slice -> local staging ----
        {
            ull b01 = 0ull, b23 = 0ull;
            #pragma unroll 16
            for (int j = 0; j < 64; ++j) {
                ull w2 = pack2(sm[W_OFF + j * WS + k2]);
                ulonglong2 p = pre2[j];
                ffma2(b01, w2, p.x);
                ffma2(b23, w2, p.y);
            }
            const int tgt = k2 >> 6, klq = (k2 & 63) * 4;
            float* o = (tgt == (int)rank) ? (sm + RED_OFF + (int)rank * 256 + klq)
                                          : (sm + RDO_OFF + tgt * 256 + klq);
            *reinterpret_cast<ulonglong2*>(o) = make_ulonglong2(b01, b23);
        }
        __syncthreads();                 // staging + self red complete

        // ---- 7 x 1KB red bulk copies ----
        if (issuer) {
            fence_async_();
            bulk_dsm(red_dst, red_src, 1024, red_mb);
        }

        // ---- owner update: wait red tx, re-arm, reduce, integrate ----
        if (tid < 256) {
            int tn = (t + 1 < T_LEN) ? (t + 1) : (T_LEN - 1);
            float tI_next = g_tanhI[row_base + (size_t)tn * NH];   // overlap wait

            mbar_wait(red_mbar, (uint32_t)(t & 1));
            if (tid == 0 && t + 1 < T_LEN) mbar_expect(red_mbar, 7168);

            float s = 0.f;
            #pragma unroll
            for (int src = 0; src < 8; ++src) s += sm[RED_OFF + src * 256 + tid];

            hz_r = hz_r + DT_C * (tI - s - g_r * hy_r - e_r * hz_r);
            hy_r = hy_r + DT_C * hz_r;
            tI = tI_next;

            sm[HYST_OFF + tid] = hy_r;                  // staging for peers
            sm[HY_OFF + (int)rank * 256 + tid] = hy_r;  // self hy block direct
        }
        __syncthreads();                 // hyst + self hy visible

        // ---- 7 x 1KB hy bulk copies first (critical path), then STG ----
        if (t + 1 < T_LEN && issuer) {
            fence_async_();
            bulk_dsm(hy_dst, hy_src, 1024, hy_mb);
        }
        if (tid < 256)                   // off critical path now
            out_states[(size_t)(m_base + m_u) * T_LEN * NH + (size_t)t * NH + k_own] = hy_r;
    }

    if (tid < 256 && out_hy)
        out_hy[(size_t)(m_base + m_u) * NH + k_own] = hy_r;

    cluster_sync_();   // keep smem alive until all peer traffic settles
}

// ---------------------------------------------------------------------------
extern "C" void kernel_launch(void* const* d_in, const int* in_sizes, int n_in,
                              void* d_out, int out_size) {
    const float* x    = (const float*)d_in[0];
    const float* x2h  = (const float*)d_in[1];
    const float* h2h  = (const float*)d_in[2];
    const float* bias = (const float*)d_in[3];
    const float* gam  = (const float*)d_in[4];
    const float* eps  = (const float*)d_in[5];
    float* out = (float*)d_out;

    const long long BTH = (long long)BSZ * T_LEN * NH;
    float* states = nullptr;
    float* hyout  = nullptr;
    if ((long long)out_size >= BTH) {
        states = out;
        if ((long long)out_size >= BTH + (long long)BSZ * NH) hyout = out + BTH;
    } else {
        hyout = out;
    }

    phase1_kernel<<<(BSZ * T_LEN) / 16, 256>>>(x, x2h);

    cudaFuncSetAttribute(rnn_kernel, cudaFuncAttributeMaxDynamicSharedMemorySize,
                         SMEM_BYTES);

    cudaLaunchConfig_t cfg = {};
    cfg.gridDim = dim3(128, 1, 1);
    cfg.blockDim = dim3(512, 1, 1);
    cfg.dynamicSmemBytes = SMEM_BYTES;
    cfg.stream = 0;
    cudaLaunchAttribute attrs[1];
    attrs[0].id = cudaLaunchAttributeClusterDimension;
    attrs[0].val.clusterDim.x = 8;
    attrs[0].val.clusterDim.y = 1;
    attrs[0].val.clusterDim.z = 1;
    cfg.attrs = attrs;
    cfg.numAttrs = 1;
    cudaLaunchKernelEx(&cfg, rnn_kernel, h2h, bias, gam, eps, states, hyout);
}

// round 14
// speedup vs baseline: 1.2750x; 1.2750x over previous
#include <cuda_runtime.h>
#include <cuda_bf16.h>
#include <cstdint>
#include <cmath>

#define T_LEN 1024
#define NH    512
#define NI    128
#define BSZ   64
#define DT_C  0.1f

// Hoisted input projection scratch: tanh(x @ x2h), [B, T, H] fp32 (134 MB).
__device__ float g_tanhI[(size_t)BSZ * T_LEN * NH];

typedef unsigned long long ull;

// ---------------------------------------------------------------------------
// helpers
// ---------------------------------------------------------------------------
__device__ __forceinline__ uint32_t smem_u32(const void* p) {
    uint32_t a;
    asm("{ .reg .u64 t; cvta.to.shared.u64 t, %1; cvt.u32.u64 %0, t; }" : "=r"(a) : "l"(p));
    return a;
}
__device__ __forceinline__ uint32_t mapa_sc(uint32_t addr, uint32_t rank) {
    uint32_t r;
    asm("mapa.shared::cluster.u32 %0, %1, %2;" : "=r"(r) : "r"(addr), "r"(rank));
    return r;
}
__device__ __forceinline__ void cluster_sync_() {
    asm volatile("barrier.cluster.arrive.aligned;" ::: "memory");
    asm volatile("barrier.cluster.wait.aligned;" ::: "memory");
}
__device__ __forceinline__ ull pack2(float w) {
    ull r;
    asm("mov.b64 %0, {%1, %1};" : "=l"(r) : "f"(w));
    return r;
}
__device__ __forceinline__ void ffma2(ull& d, ull a, ull b) {
    asm("fma.rn.f32x2 %0, %1, %2, %0;" : "+l"(d) : "l"(a), "l"(b));
}
__device__ __forceinline__ void mbar_init(uint32_t addr, uint32_t count) {
    asm volatile("mbarrier.init.shared.b64 [%0], %1;" :: "r"(addr), "r"(count) : "memory");
}
__device__ __forceinline__ void mbar_expect(uint32_t addr, uint32_t bytes) {
    asm volatile("mbarrier.arrive.expect_tx.shared.b64 _, [%0], %1;"
                 :: "r"(addr), "r"(bytes) : "memory");
}
__device__ __forceinline__ void mbar_wait(uint32_t mbar, uint32_t parity) {
    uint32_t done;
    asm volatile(
        "{\n\t.reg .pred p;\n\t"
        "mbarrier.try_wait.parity.acquire.cluster.shared::cta.b64 p, [%1], %2;\n\t"
        "selp.b32 %0, 1, 0, p;\n\t}"
        : "=r"(done) : "r"(mbar), "r"(parity) : "memory");
    if (!done) {
        asm volatile(
            "{\n\t.reg .pred P1;\n\t"
            "W_%=:\n\t"
            "mbarrier.try_wait.parity.acquire.cluster.shared::cta.b64 P1, [%0], %1, 0x989680;\n\t"
            "@P1 bra.uni D_%=;\n\t"
            "bra.uni W_%=;\n\t"
            "D_%=:\n\t}"
            :: "r"(mbar), "r"(parity) : "memory");
    }
}
__device__ __forceinline__ void fence_async_() {
    asm volatile("fence.proxy.async.shared::cta;" ::: "memory");
}
__device__ __forceinline__ void bulk_dsm(uint32_t dst_cluster, uint32_t src_cta,
                                         uint32_t bytes, uint32_t mbar_cluster) {
    asm volatile(
        "cp.async.bulk.shared::cluster.shared::cta.mbarrier::complete_tx::bytes "
        "[%0], [%1], %2, [%3];"
        :: "r"(dst_cluster), "r"(src_cta), "r"(bytes), "r"(mbar_cluster) : "memory");
}

// ---------------------------------------------------------------------------
// Phase 1: g_tanhI[bt, h] = tanh( x[bt, :] @ x2h[:, h] )
// ---------------------------------------------------------------------------
__global__ void __launch_bounds__(256) phase1_kernel(const float* __restrict__ x,
                                                     const float* __restrict__ x2h) {
    __shared__ float  x_s[16 * 132];
    __shared__ float4 w4_s[128 * 16];
    const int tid = threadIdx.x;
    const int bt0 = blockIdx.x * 16;

    for (int i = tid; i < 512; i += 256) {
        int r = i >> 5, c = i & 31;
        float4 v = *reinterpret_cast<const float4*>(x + (size_t)(bt0 + r) * NI + c * 4);
        *reinterpret_cast<float4*>(x_s + r * 132 + c * 4) = v;
    }

    const int tt = tid & 15;
    const int jc = tid >> 4;
    for (int chunk = 0; chunk < 8; ++chunk) {
        __syncthreads();
        const int jbase = chunk * 64;
        for (int i = tid; i < 2048; i += 256) {
            int k = i >> 4, jq = i & 15;
            w4_s[k * 16 + jq] =
                *reinterpret_cast<const float4*>(x2h + (size_t)k * NH + jbase + jq * 4);
        }
        __syncthreads();
        float a0 = 0.f, a1 = 0.f, a2 = 0.f, a3 = 0.f;
        #pragma unroll 8
        for (int k = 0; k < 128; ++k) {
            float  xv = x_s[tt * 132 + k];
            float4 w  = w4_s[k * 16 + jc];
            a0 = fmaf(xv, w.x, a0); a1 = fmaf(xv, w.y, a1);
            a2 = fmaf(xv, w.z, a2); a3 = fmaf(xv, w.w, a3);
        }
        float4 o = make_float4(tanhf(a0), tanhf(a1), tanhf(a2), tanhf(a3));
        *reinterpret_cast<float4*>(g_tanhI + (size_t)(bt0 + tt) * NH + jbase + jc * 4) = o;
    }
}

// ---------------------------------------------------------------------------
// Phase 2: recurrence. 16 clusters x 8 CTAs x 512 threads (R11 machinery).
// GEMM1 weight column (time-invariant, 64 floats/thread) in REGISTERS —
// loop FULLY unrolled so all indices are constants (R13's partial unroll
// demoted the array to local memory; L2% 5.6 was the smoking gun).
//
// SMEM float layout (R11):
//   [0)      wT      64*513 = 32832
//   [32832)  hy4     512*4    (hy[k][m])
//   [34880)  pre     64*4
//   [35136)  stage   8*64*4
//   [37184)  red     8*64*4   ([src][kl][m]; 1KB blocks)
//   [39232)  redout  8*64*4   (local staging [tgt][kl][m])
//   [41280)  hyst    64*4     ([kl][m])
//   [41536)  bias    64
//   [41600)  mbars   red_mbar(8B) + hy_mbar(8B) = 4 floats
//   total 41604 floats = 166416 B
// ---------------------------------------------------------------------------
#define WS        513
#define W_OFF     0
#define HY_OFF    32832
#define PRE_OFF   34880
#define STG_OFF   35136
#define RED_OFF   37184
#define RDO_OFF   39232
#define HYST_OFF  41280
#define BIAS_OFF  41536
#define MBAR_OFF  41600
#define SMEM_FLOATS 41604
#define SMEM_BYTES  (SMEM_FLOATS * 4)

__global__ void __launch_bounds__(512)
rnn_kernel(const float* __restrict__ h2h, const float* __restrict__ bias,
           const float* __restrict__ gamma_v, const float* __restrict__ eps_v,
           float* __restrict__ out_states, float* __restrict__ out_hy) {
    extern __shared__ float sm[];
    float* bias_s = sm + BIAS_OFF;
    ulonglong2* stg2 = reinterpret_cast<ulonglong2*>(sm + STG_OFF);

    const int tid = threadIdx.x;
    uint32_t rank;
    asm("mov.u32 %0, %%cluster_ctarank;" : "=r"(rank));
    const int m_base = (blockIdx.x >> 3) * 4;
    const int J0 = (int)rank * 64;
    const uint32_t smb = smem_u32(sm);
    const uint32_t red_mbar = smb + MBAR_OFF * 4;
    const uint32_t hy_mbar  = smb + MBAR_OFF * 4 + 8;

    // --- init: weights, bias, zero hy4, mbars + phase-0 arms ---
    for (int idx = tid; idx < 64 * 512; idx += 512) {
        int k = idx >> 6, jl = idx & 63;
        sm[W_OFF + jl * WS + k] = h2h[(size_t)k * NH + J0 + jl];
    }
    if (tid < 64) bias_s[tid] = bias[J0 + tid];
    for (int i = tid; i < 2048; i += 512) sm[HY_OFF + i] = 0.f;
    if (tid == 0) {
        mbar_init(red_mbar, 1);
        mbar_init(hy_mbar, 1);
        mbar_expect(red_mbar, 7168);   // 7 peers x 1KB, phase 0
        mbar_expect(hy_mbar, 7168);
    }

    // --- fixed thread mappings (R11) ---
    const int ks = tid >> 6;          // GEMM1 k-split 0..7 (64 k each)
    const int jg = tid & 63;          // GEMM1 local j
    const int k2 = tid;               // GEMM2 k (0..511)
    const int kl_u = tid >> 2;        // update (tid<256): [kl][m]
    const int m_u  = tid & 3;
    const int k_own = J0 + kl_u;

    // bulk issuers: threads 256..262, peer p = (rank + 1 + (tid-256)) & 7
    const bool issuer = (tid >= 256 && tid < 263);
    uint32_t red_dst = 0, red_src = 0, red_mb = 0;
    uint32_t hy_dst = 0, hy_src = 0, hy_mb = 0;
    if (issuer) {
        const uint32_t p = (rank + 1u + (uint32_t)(tid - 256)) & 7u;
        red_dst = mapa_sc(smb + RED_OFF * 4, p) + rank * 1024;
        red_src = smb + RDO_OFF * 4 + p * 1024;
        red_mb  = mapa_sc(red_mbar, p);
        hy_dst  = mapa_sc(smb + HY_OFF * 4, p) + rank * 1024;
        hy_src  = smb + HYST_OFF * 4;
        hy_mb   = mapa_sc(hy_mbar, p);
    }

    float hy_r = 0.f, hz_r = 0.f, g_r = 0.f, e_r = 0.f, tI = 0.f;
    size_t row_base = 0;
    if (tid < 256) {
        g_r = gamma_v[k_own];
        e_r = eps_v[k_own];
        row_base = (size_t)(m_base + m_u) * T_LEN * NH + k_own;
        tI = g_tanhI[row_base];
    }

    __syncthreads();

    // --- GEMM1 weights -> registers (FULLY unrolled: constant indices) ---
    float wreg[64];
    {
        const float* wcol = sm + W_OFF + jg * WS + ks * 64;
        #pragma unroll
        for (int k = 0; k < 64; ++k) wreg[k] = wcol[k];
    }

    cluster_sync_();   // weights / zeroed hy / armed mbars visible cluster-wide

    const ulonglong2* hyk  = reinterpret_cast<const ulonglong2*>(sm + HY_OFF) + ks * 64;
    const ulonglong2* pre2 = reinterpret_cast<const ulonglong2*>(sm + PRE_OFF);

    for (int t = 0; t < T_LEN; ++t) {
        // ---- wait hy delivery (phase t-1), re-arm next hy phase ----
        if (t) {
            mbar_wait(hy_mbar, (uint32_t)((t + 1) & 1));
            if (tid == 0 && t <= T_LEN - 2) mbar_expect(hy_mbar, 7168);
        }

        // ---- GEMM1 k-split partial: register weights, broadcast hy loads ----
        {
            ull a01 = 0ull, a23 = 0ull;
            #pragma unroll
            for (int k = 0; k < 64; ++k) {
                ull w2 = pack2(wreg[k]);
                ulonglong2 h = hyk[k];
                ffma2(a01, w2, h.x);
                ffma2(a23, w2, h.y);
            }
            stg2[ks * 64 + jg] = make_ulonglong2(a01, a23);
        }
        __syncthreads();
        if (tid < 256) {                 // sum 8 partials + bias + tanh
            float s = bias_s[tid >> 2];
            #pragma unroll
            for (int q = 0; q < 8; ++q) s += sm[STG_OFF + q * 256 + tid];
            sm[PRE_OFF + tid] = tanhf(s);
        }
        __syncthreads();

        // ---- GEMM2 partial: 1 k/thread over my 64-j slice -> local staging ----
        {
            ull b01 = 0ull, b23 = 0ull;
            #pragma unroll 16
            for (int j = 0; j < 64; ++j) {
                ull w2 = pack2(sm[W_OFF + j * WS + k2]);
                ulonglong2 p = pre2[j];
                ffma2(b01, w2, p.x);
                ffma2(b23, w2, p.y);
            }
            const int tgt = k2 >> 6, klq = (k2 & 63) * 4;
            float* o = (tgt == (int)rank) ? (sm + RED_OFF + (int)rank * 256 + klq)
                                          : (sm + RDO_OFF + tgt * 256 + klq);
            *reinterpret_cast<ulonglong2*>(o) = make_ulonglong2(b01, b23);
        }
        __syncthreads();                 // staging + self red complete

        // ---- 7 x 1KB red bulk copies ----
        if (issuer) {
            fence_async_();
            bulk_dsm(red_dst, red_src, 1024, red_mb);
        }

        // ---- owner update: wait red tx, re-arm, reduce, integrate ----
        if (tid < 256) {
            int tn = (t + 1 < T_LEN) ? (t + 1) : (T_LEN - 1);
            float tI_next = g_tanhI[row_base + (size_t)tn * NH];   // overlap wait

            mbar_wait(red_mbar, (uint32_t)(t & 1));
            if (tid == 0 && t + 1 < T_LEN) mbar_expect(red_mbar, 7168);

            float s = 0.f;
            #pragma unroll
            for (int src = 0; src < 8; ++src) s += sm[RED_OFF + src * 256 + tid];

            hz_r = hz_r + DT_C * (tI - s - g_r * hy_r - e_r * hz_r);
            hy_r = hy_r + DT_C * hz_r;
            tI = tI_next;

            sm[HYST_OFF + tid] = hy_r;                  // staging for peers
            sm[HY_OFF + (int)rank * 256 + tid] = hy_r;  // self hy block direct
        }
        __syncthreads();                 // hyst + self hy visible

        // ---- 7 x 1KB hy bulk copies first (critical path), then STG ----
        if (t + 1 < T_LEN && issuer) {
            fence_async_();
            bulk_dsm(hy_dst, hy_src, 1024, hy_mb);
        }
        if (tid < 256)                   // off critical path now
            out_states[(size_t)(m_base + m_u) * T_LEN * NH + (size_t)t * NH + k_own] = hy_r;
    }

    if (tid < 256 && out_hy)
        out_hy[(size_t)(m_base + m_u) * NH + k_own] = hy_r;

    cluster_sync_();   // keep smem alive until all peer traffic settles
}

// ---------------------------------------------------------------------------
extern "C" void kernel_launch(void* const* d_in, const int* in_sizes, int n_in,
                              void* d_out, int out_size) {
    const float* x    = (const float*)d_in[0];
    const float* x2h  = (const float*)d_in[1];
    const float* h2h  = (const float*)d_in[2];
    const float* bias = (const float*)d_in[3];
    const float* gam  = (const float*)d_in[4];
    const float* eps  = (const float*)d_in[5];
    float* out = (float*)d_out;

    const long long BTH = (long long)BSZ * T_LEN * NH;
    float* states = nullptr;
    float* hyout  = nullptr;
    if ((long long)out_size >= BTH) {
        states = out;
        if ((long long)out_size >= BTH + (long long)BSZ * NH) hyout = out + BTH;
    } else {
        hyout = out;
    }

    phase1_kernel<<<(BSZ * T_LEN) / 16, 256>>>(x, x2h);

    cudaFuncSetAttribute(rnn_kernel, cudaFuncAttributeMaxDynamicSharedMemorySize,
                         SMEM_BYTES);

    cudaLaunchConfig_t cfg = {};
    cfg.gridDim = dim3(128, 1, 1);
    cfg.blockDim = dim3(512, 1, 1);
    cfg.dynamicSmemBytes = SMEM_BYTES;
    cfg.stream = 0;
    cudaLaunchAttribute attrs[1];
    attrs[0].id = cudaLaunchAttributeClusterDimension;
    attrs[0].val.clusterDim.x = 8;
    attrs[0].val.clusterDim.y = 1;
    attrs[0].val.clusterDim.z = 1;
    cfg.attrs = attrs;
    cfg.numAttrs = 1;
    cudaLaunchKernelEx(&cfg, rnn_kernel, h2h, bias, gam, eps, states, hyout);
}